// round 12
// baseline (speedup 1.0000x reference)
#include <cuda_runtime.h>
#include <math.h>

#define NB_   1024
#define NS    500
#define RG    128
#define NLAT  12
#define NFEAT 64
#define NHID  128
#define NPTS  (NB_*NS)
#define NROW  21          // 9 raw inputs + 12 folded latents
#define KPAD  24          // NROW padded to 24 floats (12 f32x2 pairs)

// Scratch (static device arrays: no allocation allowed)
__device__ float4 g_rgbs[NPTS];          // (r, g, b, sdf) - active entries only
__device__ float  g_W1eff[NLAT*NHID];    // folded Wf @ W1[9:73]
__device__ float  g_b1eff[NHID];         // b1 + bf @ W1[9:73]
__device__ int    g_act_list[NPTS];      // packed (ray<<9)|s for active samples
__device__ int    g_slo[NB_];            // first active s per ray
__device__ int    g_scnt[NB_];           // active count per ray
__device__ int    g_total;               // total active samples
__device__ float  g_inT[22*NPTS];        // transposed MLP inputs: [k][i], k=21 is sdf

// ---- packed f32x2 helpers -------------------------------------------------
typedef unsigned long long ull;
__device__ __forceinline__ ull ffma2(ull a, ull b, ull c) {
    ull d;
    asm("fma.rn.f32x2 %0, %1, %2, %3;" : "=l"(d) : "l"(a), "l"(b), "l"(c));
    return d;
}
__device__ __forceinline__ ull pack2(float lo, float hi) {
    ull r;
    asm("mov.b64 %0, {%1, %2};" : "=l"(r) : "f"(lo), "f"(hi));
    return r;
}
__device__ __forceinline__ void unpack2(ull u, float& lo, float& hi) {
    asm("mov.b64 {%0, %1}, %2;" : "=f"(lo), "=f"(hi) : "l"(u));
}

// ---------------------------------------------------------------------------
__global__ __launch_bounds__(256)
void prep_kernel(const float* __restrict__ Wf,
                 const float* __restrict__ bf,
                 const float* __restrict__ W1,
                 const float* __restrict__ b1)
{
    int tid = threadIdx.x;
    if (tid == 0) g_total = 0;
    for (int e = tid; e < NLAT*NHID; e += 256) {
        int l = e >> 7, j = e & 127;
        float acc = 0.f;
        #pragma unroll 8
        for (int f = 0; f < NFEAT; f++)
            acc = fmaf(Wf[l*NFEAT + f], W1[(9+f)*NHID + j], acc);
        g_W1eff[e] = acc;
    }
    for (int j = tid; j < NHID; j += 256) {
        float acc = b1[j];
        #pragma unroll 8
        for (int f = 0; f < NFEAT; f++)
            acc = fmaf(bf[f], W1[(9+f)*NHID + j], acc);
        g_b1eff[j] = acc;
    }
}

// ---------------------------------------------------------------------------
// interval_kernel: one warp per ray; ballot -> contiguous [first,last], compact.
// ---------------------------------------------------------------------------
__global__ __launch_bounds__(256)
void interval_kernel(const float* __restrict__ rays_o,
                     const float* __restrict__ rays_d)
{
    int warp = (blockIdx.x*blockDim.x + threadIdx.x) >> 5;
    int lane = threadIdx.x & 31;
    if (warp >= NB_) return;
    int ray = warp;

    float ox = __ldg(&rays_o[3*ray+0]), oy = __ldg(&rays_o[3*ray+1]),
          oz = __ldg(&rays_o[3*ray+2]);
    float dx = __ldg(&rays_d[3*ray+0]), dy = __ldg(&rays_d[3*ray+1]),
          dz = __ldg(&rays_d[3*ray+2]);

    int first = -1, last = -1;
    #pragma unroll
    for (int c = 0; c < 16; c++) {
        int s = c*32 + lane;
        float z  = 0.5f + 3.0f*((float)s * (1.0f/499.0f));
        float px = fmaf(dx, z, ox), py = fmaf(dy, z, oy), pz = fmaf(dz, z, oz);
        bool act = (s < NS) &
                   (px >= -1.f) & (px <= 1.f) &
                   (py >= -1.f) & (py <= 1.f) &
                   (pz >= -1.f) & (pz <= 1.f);
        unsigned m = __ballot_sync(0xffffffffu, act);
        if (m) {
            if (first < 0) first = c*32 + (__ffs(m) - 1);
            last = c*32 + (31 - __clz(m));
        }
    }
    int cnt = (first >= 0) ? (last - first + 1) : 0;

    int off = 0;
    if (lane == 0) {
        g_slo[ray]  = first;
        g_scnt[ray] = cnt;
        if (cnt > 0) off = atomicAdd(&g_total, cnt);
    }
    off = __shfl_sync(0xffffffffu, off, 0);

    if (cnt > 0) {
        for (int s = first + lane; s <= last; s += 32)
            g_act_list[off + (s - first)] = (ray << 9) | s;
    }
}

// ---------------------------------------------------------------------------
// Kernel T: trilerp + grad, one point per thread, HIGH occupancy.
// Writes transposed inputs g_inT[k][i] (coalesced per k) + sdf at k=21.
// ---------------------------------------------------------------------------
__global__ __launch_bounds__(128, 8)
void trilerp_kernel(const float* __restrict__ rays_o,
                    const float* __restrict__ rays_d,
                    const float* __restrict__ viewdirs,
                    const float* __restrict__ grid)
{
    const int OX = RG*RG*13, OY = RG*13, OZ = 13;
    int total  = g_total;
    int gid    = blockIdx.x*blockDim.x + threadIdx.x;
    int stride = gridDim.x*blockDim.x;

    for (int i = gid; i < total; i += stride) {
        int ia = g_act_list[i];
        int r = ia >> 9, s = ia & 511;

        float z  = 0.5f + 3.0f*((float)s * (1.0f/499.0f));
        float px = fmaf(__ldg(&rays_d[3*r+0]), z, __ldg(&rays_o[3*r+0]));
        float py = fmaf(__ldg(&rays_d[3*r+1]), z, __ldg(&rays_o[3*r+1]));
        float pz = fmaf(__ldg(&rays_d[3*r+2]), z, __ldg(&rays_o[3*r+2]));

        float ux = (px + 1.f)*63.5f, uy = (py + 1.f)*63.5f, uz = (pz + 1.f)*63.5f;
        int ix = min((int)ux, 126), iy = min((int)uy, 126), iz = min((int)uz, 126);
        float fx = ux - (float)ix, fy = uy - (float)iy, fz = uz - (float)iz;
        float wx0 = 1.f-fx, wx1 = fx, wy0 = 1.f-fy, wy1 = fy,
              wz0 = 1.f-fz, wz1 = fz;

        const float* gp = grid + ((size_t)(ix*RG + iy)*RG + iz)*13;

        float vals[13];
        #pragma unroll
        for (int c = 0; c < 13; c++) vals[c] = 0.f;
        float c0a[8];
        #pragma unroll
        for (int cc = 0; cc < 8; cc++) {
            int dx = cc >> 2, dy = (cc >> 1) & 1, dz = cc & 1;
            const float* p = gp + dx*OX + dy*OY + dz*OZ;
            float w = (dx ? wx1 : wx0) * (dy ? wy1 : wy0) * (dz ? wz1 : wz0);
            float v0 = __ldg(p);
            c0a[cc] = v0;
            vals[0] = fmaf(w, v0, vals[0]);
            #pragma unroll
            for (int c = 1; c < 13; c++) vals[c] = fmaf(w, __ldg(p + c), vals[c]);
        }
        float gx = 63.5f*( wy0*wz0*(c0a[4]-c0a[0]) + wy0*wz1*(c0a[5]-c0a[1])
                         + wy1*wz0*(c0a[6]-c0a[2]) + wy1*wz1*(c0a[7]-c0a[3]) );
        float gy = 63.5f*( wx0*wz0*(c0a[2]-c0a[0]) + wx0*wz1*(c0a[3]-c0a[1])
                         + wx1*wz0*(c0a[6]-c0a[4]) + wx1*wz1*(c0a[7]-c0a[5]) );
        float gz = 63.5f*( wx0*wy0*(c0a[1]-c0a[0]) + wx0*wy1*(c0a[3]-c0a[2])
                         + wx1*wy0*(c0a[5]-c0a[4]) + wx1*wy1*(c0a[7]-c0a[6]) );

        g_inT[ 0*NPTS + i] = px;
        g_inT[ 1*NPTS + i] = py;
        g_inT[ 2*NPTS + i] = pz;
        g_inT[ 3*NPTS + i] = gx;
        g_inT[ 4*NPTS + i] = gy;
        g_inT[ 5*NPTS + i] = gz;
        g_inT[ 6*NPTS + i] = __ldg(&viewdirs[3*r+0]);
        g_inT[ 7*NPTS + i] = __ldg(&viewdirs[3*r+1]);
        g_inT[ 8*NPTS + i] = __ldg(&viewdirs[3*r+2]);
        #pragma unroll
        for (int l = 0; l < NLAT; l++)
            g_inT[(9+l)*NPTS + i] = vals[1+l];
        g_inT[21*NPTS + i] = vals[0];
    }
}

// ---------------------------------------------------------------------------
// Kernel M: MLP only, ONE point per thread, k-packed fma.rn.f32x2.
// ---------------------------------------------------------------------------
__global__ __launch_bounds__(128, 6)
void mlp_kernel(const float* __restrict__ W1,
                const float* __restrict__ W2,
                const float* __restrict__ b2)
{
    __shared__ __align__(16) float sW1t[NHID*KPAD];  // [j][k], k padded to 24
    __shared__ __align__(16) float sW2t[3*NHID];     // [c][j]
    __shared__ __align__(16) float sb1[NHID];
    __shared__ float sb2[4];

    // build transposed+padded W1 (rows 0-8 raw, 9-20 folded, 21-23 zero)
    for (int e = threadIdx.x; e < NHID*KPAD; e += blockDim.x) {
        int j = e / KPAD, k = e - j*KPAD;
        float v = 0.f;
        if (k < 9)          v = W1[k*NHID + j];
        else if (k < NROW)  v = g_W1eff[(k-9)*NHID + j];
        sW1t[e] = v;
    }
    for (int i = threadIdx.x; i < NHID; i += blockDim.x) sb1[i] = g_b1eff[i];
    for (int i = threadIdx.x; i < NHID*3; i += blockDim.x) {
        int j = i / 3, c = i - 3*j;
        sW2t[c*NHID + j] = W2[i];
    }
    if (threadIdx.x < 3) sb2[threadIdx.x] = b2[threadIdx.x];
    __syncthreads();

    int total  = g_total;
    int gid    = blockIdx.x*blockDim.x + threadIdx.x;
    int stride = gridDim.x*blockDim.x;

    for (int i = gid; i < total; i += stride) {
        float in[NROW];
        #pragma unroll
        for (int k = 0; k < NROW; k++)
            in[k] = __ldg(&g_inT[k*NPTS + i]);
        float sdf = __ldg(&g_inT[21*NPTS + i]);

        ull h2[12];
        #pragma unroll
        for (int q = 0; q < 10; q++) h2[q] = pack2(in[2*q], in[2*q+1]);
        h2[10] = pack2(in[20], 0.f);
        h2[11] = 0ull;

        ull op0 = 0ull, op1 = 0ull, op2 = 0ull;
        #pragma unroll 4
        for (int j = 0; j < NHID; j += 2) {
            const ulonglong2* r0 = (const ulonglong2*)&sW1t[j*KPAD];
            const ulonglong2* r1 = (const ulonglong2*)&sW1t[(j+1)*KPAD];
            ull a0 = 0ull, a1 = 0ull, b0 = 0ull, b1 = 0ull;
            #pragma unroll
            for (int q = 0; q < 6; q++) {
                ulonglong2 w0 = r0[q];
                ulonglong2 w1 = r1[q];
                a0 = ffma2(h2[2*q],   w0.x, a0);
                a1 = ffma2(h2[2*q+1], w0.y, a1);
                b0 = ffma2(h2[2*q],   w1.x, b0);
                b1 = ffma2(h2[2*q+1], w1.y, b1);
            }
            float a0l,a0h,a1l,a1h,b0l,b0h,b1l,b1h;
            unpack2(a0, a0l, a0h); unpack2(a1, a1l, a1h);
            unpack2(b0, b0l, b0h); unpack2(b1, b1l, b1h);
            float hA = fmaxf(((a0l + a0h) + (a1l + a1h)) + sb1[j],   0.f);
            float hB = fmaxf(((b0l + b0h) + (b1l + b1h)) + sb1[j+1], 0.f);
            ull hp = pack2(hA, hB);
            op0 = ffma2(hp, *(const ull*)&sW2t[0*NHID + j], op0);
            op1 = ffma2(hp, *(const ull*)&sW2t[1*NHID + j], op1);
            op2 = ffma2(hp, *(const ull*)&sW2t[2*NHID + j], op2);
        }
        float s0l,s0h,s1l,s1h,s2l,s2h;
        unpack2(op0, s0l, s0h);
        unpack2(op1, s1l, s1h);
        unpack2(op2, s2l, s2h);
        float o0 = s0l + s0h + sb2[0];
        float o1 = s1l + s1h + sb2[1];
        float o2 = s2l + s2h + sb2[2];

        int pa = g_act_list[i];
        g_rgbs[(pa >> 9)*NS + (pa & 511)] =
            make_float4(1.f/(1.f + expf(-o0)),
                        1.f/(1.f + expf(-o1)),
                        1.f/(1.f + expf(-o2)), sdf);
    }
}

// ---------------------------------------------------------------------------
// Kernel B: per-ray transmittance scan. One warp (=one block) per ray.
// ---------------------------------------------------------------------------
__global__ __launch_bounds__(32)
void ray_kernel(const float* __restrict__ rays_d,
                const float* __restrict__ beta_p,
                float* __restrict__ out)
{
    int ray  = blockIdx.x;
    int lane = threadIdx.x;

    float be    = fabsf(__ldg(beta_p)) + 1e-4f;
    float inv_b = 1.0f / be;
    float d0 = __ldg(&rays_d[3*ray+0]);
    float d1 = __ldg(&rays_d[3*ray+1]);
    float d2 = __ldg(&rays_d[3*ray+2]);
    float dn = sqrtf(d0*d0 + d1*d1 + d2*d2);

    int slo = g_slo[ray];
    int scnt = g_scnt[ray];
    int shi = slo + scnt;

    const float4* vp = g_rgbs + (size_t)ray*NS;
    const float dist = 3.0f/499.0f;

    float4 v[16];
    #pragma unroll
    for (int c = 0; c < 16; c++) {
        int s = c*32 + lane;
        bool in = (scnt > 0) & (s >= slo) & (s < shi) & (s < NS);
        v[c] = in ? __ldg(&vp[s]) : make_float4(0.f, 0.f, 0.f, 100.f);
    }

    float fe[16];
    #pragma unroll
    for (int c = 0; c < 16; c++) {
        float sdf = v[c].w;
        float as  = fabsf(sdf);
        float sg  = (sdf > 0.f) ? 1.f : ((sdf < 0.f) ? -1.f : 0.f);
        float dens = inv_b * (0.5f + 0.5f*sg*expm1f(-as*inv_b));
        fe[c] = dist * dens;
    }

    float inc[16];
    #pragma unroll
    for (int c = 0; c < 16; c++) {
        float x = fe[c];
        #pragma unroll
        for (int o = 1; o < 32; o <<= 1) {
            float n = __shfl_up_sync(0xffffffffu, x, o);
            if (lane >= o) x += n;
        }
        inc[c] = x;
    }

    float carry = 0.f, r0 = 0.f, r1 = 0.f, r2 = 0.f, dep = 0.f;
    #pragma unroll
    for (int c = 0; c < 16; c++) {
        float excl  = carry + (inc[c] - fe[c]);
        float T     = expf(-excl);
        float alpha = 1.f - expf(-fe[c]);
        float w     = alpha * T;
        int   s     = c*32 + lane;
        float zs    = 0.5f + 3.0f*((float)s * (1.0f/499.0f));
        if (s < NS) {
            r0  += w * v[c].x;
            r1  += w * v[c].y;
            r2  += w * v[c].z;
            dep += w * zs * dn;
        }
        carry += __shfl_sync(0xffffffffu, inc[c], 31);
    }

    #pragma unroll
    for (int o = 16; o > 0; o >>= 1) {
        r0  += __shfl_xor_sync(0xffffffffu, r0,  o);
        r1  += __shfl_xor_sync(0xffffffffu, r1,  o);
        r2  += __shfl_xor_sync(0xffffffffu, r2,  o);
        dep += __shfl_xor_sync(0xffffffffu, dep, o);
    }
    if (lane == 0) {
        out[3*ray+0]     = r0;
        out[3*ray+1]     = r1;
        out[3*ray+2]     = r2;
        out[3*NB_ + ray] = dep;
    }
}

// ---------------------------------------------------------------------------
extern "C" void kernel_launch(void* const* d_in, const int* in_sizes, int n_in,
                              void* d_out, int out_size)
{
    const float* rays_o   = (const float*)d_in[0];
    const float* rays_d   = (const float*)d_in[1];
    const float* viewdirs = (const float*)d_in[2];
    const float* grid     = (const float*)d_in[3];
    const float* Wf       = (const float*)d_in[4];
    const float* bf       = (const float*)d_in[5];
    const float* W1       = (const float*)d_in[6];
    const float* b1       = (const float*)d_in[7];
    const float* W2       = (const float*)d_in[8];
    const float* b2       = (const float*)d_in[9];
    const float* beta     = (const float*)d_in[10];

    // ncu captures our 0-based launch index 3 -> mlp_kernel there.
    prep_kernel<<<1, 256>>>(Wf, bf, W1, b1);                 // resets g_total
    interval_kernel<<<NB_/8, 256>>>(rays_o, rays_d);
    trilerp_kernel<<<1184, 128>>>(rays_o, rays_d, viewdirs, grid);
    mlp_kernel<<<888, 128>>>(W1, W2, b2);
    ray_kernel<<<NB_, 32>>>(rays_d, beta, (float*)d_out);
}

// round 13
// speedup vs baseline: 1.1186x; 1.1186x over previous
#include <cuda_runtime.h>
#include <math.h>

#define NB_   1024
#define NS    500
#define RG    128
#define NLAT  12
#define NFEAT 64
#define NHID  128
#define NPTS  (NB_*NS)
#define NROW  21          // 9 raw inputs + 12 folded latents
#define MTILE 64          // points per block tile

// Scratch (static device arrays: no allocation allowed)
__device__ float4 g_rgbs[NPTS];          // (r, g, b, sdf) - active entries only
__device__ float  g_W1eff[NLAT*NHID];    // folded Wf @ W1[9:73]
__device__ float  g_b1eff[NHID];         // b1 + bf @ W1[9:73]
__device__ int    g_act_list[NPTS];      // packed (ray<<9)|s for active samples
__device__ int    g_slo[NB_];            // first active s per ray
__device__ int    g_scnt[NB_];           // active count per ray
__device__ int    g_total;               // total active samples
__device__ float  g_inT[22*NPTS];        // transposed MLP inputs: [k][i], k=21 is sdf

// ---------------------------------------------------------------------------
__global__ __launch_bounds__(256)
void prep_kernel(const float* __restrict__ Wf,
                 const float* __restrict__ bf,
                 const float* __restrict__ W1,
                 const float* __restrict__ b1)
{
    int tid = threadIdx.x;
    if (tid == 0) g_total = 0;
    for (int e = tid; e < NLAT*NHID; e += 256) {
        int l = e >> 7, j = e & 127;
        float acc = 0.f;
        #pragma unroll 8
        for (int f = 0; f < NFEAT; f++)
            acc = fmaf(Wf[l*NFEAT + f], W1[(9+f)*NHID + j], acc);
        g_W1eff[e] = acc;
    }
    for (int j = tid; j < NHID; j += 256) {
        float acc = b1[j];
        #pragma unroll 8
        for (int f = 0; f < NFEAT; f++)
            acc = fmaf(bf[f], W1[(9+f)*NHID + j], acc);
        g_b1eff[j] = acc;
    }
}

// ---------------------------------------------------------------------------
// interval_kernel: one warp per ray; ballot -> contiguous [first,last], compact.
// ---------------------------------------------------------------------------
__global__ __launch_bounds__(256)
void interval_kernel(const float* __restrict__ rays_o,
                     const float* __restrict__ rays_d)
{
    int warp = (blockIdx.x*blockDim.x + threadIdx.x) >> 5;
    int lane = threadIdx.x & 31;
    if (warp >= NB_) return;
    int ray = warp;

    float ox = __ldg(&rays_o[3*ray+0]), oy = __ldg(&rays_o[3*ray+1]),
          oz = __ldg(&rays_o[3*ray+2]);
    float dx = __ldg(&rays_d[3*ray+0]), dy = __ldg(&rays_d[3*ray+1]),
          dz = __ldg(&rays_d[3*ray+2]);

    int first = -1, last = -1;
    #pragma unroll
    for (int c = 0; c < 16; c++) {
        int s = c*32 + lane;
        float z  = 0.5f + 3.0f*((float)s * (1.0f/499.0f));
        float px = fmaf(dx, z, ox), py = fmaf(dy, z, oy), pz = fmaf(dz, z, oz);
        bool act = (s < NS) &
                   (px >= -1.f) & (px <= 1.f) &
                   (py >= -1.f) & (py <= 1.f) &
                   (pz >= -1.f) & (pz <= 1.f);
        unsigned m = __ballot_sync(0xffffffffu, act);
        if (m) {
            if (first < 0) first = c*32 + (__ffs(m) - 1);
            last = c*32 + (31 - __clz(m));
        }
    }
    int cnt = (first >= 0) ? (last - first + 1) : 0;

    int off = 0;
    if (lane == 0) {
        g_slo[ray]  = first;
        g_scnt[ray] = cnt;
        if (cnt > 0) off = atomicAdd(&g_total, cnt);
    }
    off = __shfl_sync(0xffffffffu, off, 0);

    if (cnt > 0) {
        for (int s = first + lane; s <= last; s += 32)
            g_act_list[off + (s - first)] = (ray << 9) | s;
    }
}

// ---------------------------------------------------------------------------
// Kernel T: trilerp + grad, one point per thread, HIGH occupancy.
// Writes transposed inputs g_inT[k][i] (coalesced per k) + sdf at k=21.
// ---------------------------------------------------------------------------
__global__ __launch_bounds__(128, 8)
void trilerp_kernel(const float* __restrict__ rays_o,
                    const float* __restrict__ rays_d,
                    const float* __restrict__ viewdirs,
                    const float* __restrict__ grid)
{
    const int OX = RG*RG*13, OY = RG*13, OZ = 13;
    int total  = g_total;
    int gid    = blockIdx.x*blockDim.x + threadIdx.x;
    int stride = gridDim.x*blockDim.x;

    for (int i = gid; i < total; i += stride) {
        int ia = g_act_list[i];
        int r = ia >> 9, s = ia & 511;

        float z  = 0.5f + 3.0f*((float)s * (1.0f/499.0f));
        float px = fmaf(__ldg(&rays_d[3*r+0]), z, __ldg(&rays_o[3*r+0]));
        float py = fmaf(__ldg(&rays_d[3*r+1]), z, __ldg(&rays_o[3*r+1]));
        float pz = fmaf(__ldg(&rays_d[3*r+2]), z, __ldg(&rays_o[3*r+2]));

        float ux = (px + 1.f)*63.5f, uy = (py + 1.f)*63.5f, uz = (pz + 1.f)*63.5f;
        int ix = min((int)ux, 126), iy = min((int)uy, 126), iz = min((int)uz, 126);
        float fx = ux - (float)ix, fy = uy - (float)iy, fz = uz - (float)iz;
        float wx0 = 1.f-fx, wx1 = fx, wy0 = 1.f-fy, wy1 = fy,
              wz0 = 1.f-fz, wz1 = fz;

        const float* gp = grid + ((size_t)(ix*RG + iy)*RG + iz)*13;

        float vals[13];
        #pragma unroll
        for (int c = 0; c < 13; c++) vals[c] = 0.f;
        float c0a[8];
        #pragma unroll
        for (int cc = 0; cc < 8; cc++) {
            int dx = cc >> 2, dy = (cc >> 1) & 1, dz = cc & 1;
            const float* p = gp + dx*OX + dy*OY + dz*OZ;
            float w = (dx ? wx1 : wx0) * (dy ? wy1 : wy0) * (dz ? wz1 : wz0);
            float v0 = __ldg(p);
            c0a[cc] = v0;
            vals[0] = fmaf(w, v0, vals[0]);
            #pragma unroll
            for (int c = 1; c < 13; c++) vals[c] = fmaf(w, __ldg(p + c), vals[c]);
        }
        float gx = 63.5f*( wy0*wz0*(c0a[4]-c0a[0]) + wy0*wz1*(c0a[5]-c0a[1])
                         + wy1*wz0*(c0a[6]-c0a[2]) + wy1*wz1*(c0a[7]-c0a[3]) );
        float gy = 63.5f*( wx0*wz0*(c0a[2]-c0a[0]) + wx0*wz1*(c0a[3]-c0a[1])
                         + wx1*wz0*(c0a[6]-c0a[4]) + wx1*wz1*(c0a[7]-c0a[5]) );
        float gz = 63.5f*( wx0*wy0*(c0a[1]-c0a[0]) + wx0*wy1*(c0a[3]-c0a[2])
                         + wx1*wy0*(c0a[5]-c0a[4]) + wx1*wy1*(c0a[7]-c0a[6]) );

        g_inT[ 0*NPTS + i] = px;
        g_inT[ 1*NPTS + i] = py;
        g_inT[ 2*NPTS + i] = pz;
        g_inT[ 3*NPTS + i] = gx;
        g_inT[ 4*NPTS + i] = gy;
        g_inT[ 5*NPTS + i] = gz;
        g_inT[ 6*NPTS + i] = __ldg(&viewdirs[3*r+0]);
        g_inT[ 7*NPTS + i] = __ldg(&viewdirs[3*r+1]);
        g_inT[ 8*NPTS + i] = __ldg(&viewdirs[3*r+2]);
        #pragma unroll
        for (int l = 0; l < NLAT; l++)
            g_inT[(9+l)*NPTS + i] = vals[1+l];
        g_inT[21*NPTS + i] = vals[0];
    }
}

// ---------------------------------------------------------------------------
// Kernel M: register-tiled GEMM MLP.
// Block = 128 threads (8 pt-rows x 16 hid-cols); tile = 64 pts x 128 hidden.
// Each thread: 8x8 fp32 accumulator; k-loop does 4 LDS.128 per 64 FMA.
// ---------------------------------------------------------------------------
__global__ __launch_bounds__(128, 4)
void mlp_kernel(const float* __restrict__ W1,
                const float* __restrict__ W2,
                const float* __restrict__ b2)
{
    __shared__ __align__(16) float sW[NROW*NHID];    // [k][j]: 0-8 raw, 9-20 folded
    __shared__ __align__(16) float sA[NROW*MTILE];   // [k][p] input tile
    __shared__ __align__(16) float sW2t[3*NHID];     // [c][j]
    __shared__ __align__(16) float sb1[NHID];
    __shared__ float sb2[4];

    for (int i = threadIdx.x; i < 9*NHID; i += blockDim.x) sW[i] = W1[i];
    for (int i = threadIdx.x; i < NLAT*NHID; i += blockDim.x)
        sW[9*NHID + i] = g_W1eff[i];
    for (int i = threadIdx.x; i < NHID; i += blockDim.x) sb1[i] = g_b1eff[i];
    for (int i = threadIdx.x; i < NHID*3; i += blockDim.x) {
        int j = i / 3, c = i - 3*j;
        sW2t[c*NHID + j] = W2[i];
    }
    if (threadIdx.x < 3) sb2[threadIdx.x] = b2[threadIdx.x];

    int total = g_total;
    int ptrow  = threadIdx.x >> 4;      // 0..7
    int hidcol = threadIdx.x & 15;      // 0..15
    int hbase  = hidcol * 8;

    for (int base = blockIdx.x*MTILE; base < total; base += gridDim.x*MTILE) {
        __syncthreads();   // protect sA from previous tile (also covers weight init)
        // cooperative A-tile load: 21 rows x 64 floats, coalesced
        for (int e = threadIdx.x; e < NROW*MTILE; e += blockDim.x) {
            int k = e >> 6, p = e & 63;
            int i = base + p;
            sA[k*MTILE + p] = (i < total) ? g_inT[k*NPTS + i] : 0.f;
        }
        __syncthreads();

        float acc[8][8];
        #pragma unroll
        for (int p = 0; p < 8; p++)
            #pragma unroll
            for (int h = 0; h < 8; h++) acc[p][h] = 0.f;

        #pragma unroll 3
        for (int k = 0; k < NROW; k++) {
            float4 a0 = *(const float4*)&sA[k*MTILE + ptrow*8];
            float4 a1 = *(const float4*)&sA[k*MTILE + ptrow*8 + 4];
            float4 w0 = *(const float4*)&sW[k*NHID + hbase];
            float4 w1 = *(const float4*)&sW[k*NHID + hbase + 4];
            float av[8] = {a0.x,a0.y,a0.z,a0.w,a1.x,a1.y,a1.z,a1.w};
            float wv[8] = {w0.x,w0.y,w0.z,w0.w,w1.x,w1.y,w1.z,w1.w};
            #pragma unroll
            for (int p = 0; p < 8; p++)
                #pragma unroll
                for (int h = 0; h < 8; h++)
                    acc[p][h] = fmaf(av[p], wv[h], acc[p][h]);
        }

        // bias + relu (in place), then fold W2 -> po[3][8pts]
        float4 bA = *(const float4*)&sb1[hbase];
        float4 bB = *(const float4*)&sb1[hbase + 4];
        float bv[8] = {bA.x,bA.y,bA.z,bA.w,bB.x,bB.y,bB.z,bB.w};
        #pragma unroll
        for (int p = 0; p < 8; p++)
            #pragma unroll
            for (int h = 0; h < 8; h++)
                acc[p][h] = fmaxf(acc[p][h] + bv[h], 0.f);

        float po[3][8];
        #pragma unroll
        for (int c = 0; c < 3; c++) {
            float4 wA = *(const float4*)&sW2t[c*NHID + hbase];
            float4 wB = *(const float4*)&sW2t[c*NHID + hbase + 4];
            float wv[8] = {wA.x,wA.y,wA.z,wA.w,wB.x,wB.y,wB.z,wB.w};
            #pragma unroll
            for (int p = 0; p < 8; p++) {
                float t = 0.f;
                #pragma unroll
                for (int h = 0; h < 8; h++)
                    t = fmaf(acc[p][h], wv[h], t);
                po[c][p] = t;
            }
        }

        // butterfly reduce over the 16 hid-cols (lanes l = ptrow*16 + hidcol;
        // 16-lane groups are warp-halves, xor offsets 8,4,2,1 stay inside)
        #pragma unroll
        for (int o = 8; o >= 1; o >>= 1) {
            #pragma unroll
            for (int c = 0; c < 3; c++)
                #pragma unroll
                for (int p = 0; p < 8; p++)
                    po[c][p] += __shfl_xor_sync(0xffffffffu, po[c][p], o);
        }

        // lanes hidcol 0..7 each store one point (p = hidcol)
        if (hidcol < 8) {
            float o0 = sb2[0], o1 = sb2[1], o2 = sb2[2];
            #pragma unroll
            for (int p = 0; p < 8; p++) {
                if (p == hidcol) { o0 += po[0][p]; o1 += po[1][p]; o2 += po[2][p]; }
            }
            int i = base + ptrow*8 + hidcol;
            if (i < total) {
                float sdf = __ldg(&g_inT[21*NPTS + i]);
                int pa = g_act_list[i];
                g_rgbs[(pa >> 9)*NS + (pa & 511)] =
                    make_float4(1.f/(1.f + expf(-o0)),
                                1.f/(1.f + expf(-o1)),
                                1.f/(1.f + expf(-o2)), sdf);
            }
        }
    }
}

// ---------------------------------------------------------------------------
// Kernel B: per-ray transmittance scan. One warp (=one block) per ray.
// ---------------------------------------------------------------------------
__global__ __launch_bounds__(32)
void ray_kernel(const float* __restrict__ rays_d,
                const float* __restrict__ beta_p,
                float* __restrict__ out)
{
    int ray  = blockIdx.x;
    int lane = threadIdx.x;

    float be    = fabsf(__ldg(beta_p)) + 1e-4f;
    float inv_b = 1.0f / be;
    float d0 = __ldg(&rays_d[3*ray+0]);
    float d1 = __ldg(&rays_d[3*ray+1]);
    float d2 = __ldg(&rays_d[3*ray+2]);
    float dn = sqrtf(d0*d0 + d1*d1 + d2*d2);

    int slo = g_slo[ray];
    int scnt = g_scnt[ray];
    int shi = slo + scnt;

    const float4* vp = g_rgbs + (size_t)ray*NS;
    const float dist = 3.0f/499.0f;

    float4 v[16];
    #pragma unroll
    for (int c = 0; c < 16; c++) {
        int s = c*32 + lane;
        bool in = (scnt > 0) & (s >= slo) & (s < shi) & (s < NS);
        v[c] = in ? __ldg(&vp[s]) : make_float4(0.f, 0.f, 0.f, 100.f);
    }

    float fe[16];
    #pragma unroll
    for (int c = 0; c < 16; c++) {
        float sdf = v[c].w;
        float as  = fabsf(sdf);
        float sg  = (sdf > 0.f) ? 1.f : ((sdf < 0.f) ? -1.f : 0.f);
        float dens = inv_b * (0.5f + 0.5f*sg*expm1f(-as*inv_b));
        fe[c] = dist * dens;
    }

    float inc[16];
    #pragma unroll
    for (int c = 0; c < 16; c++) {
        float x = fe[c];
        #pragma unroll
        for (int o = 1; o < 32; o <<= 1) {
            float n = __shfl_up_sync(0xffffffffu, x, o);
            if (lane >= o) x += n;
        }
        inc[c] = x;
    }

    float carry = 0.f, r0 = 0.f, r1 = 0.f, r2 = 0.f, dep = 0.f;
    #pragma unroll
    for (int c = 0; c < 16; c++) {
        float excl  = carry + (inc[c] - fe[c]);
        float T     = expf(-excl);
        float alpha = 1.f - expf(-fe[c]);
        float w     = alpha * T;
        int   s     = c*32 + lane;
        float zs    = 0.5f + 3.0f*((float)s * (1.0f/499.0f));
        if (s < NS) {
            r0  += w * v[c].x;
            r1  += w * v[c].y;
            r2  += w * v[c].z;
            dep += w * zs * dn;
        }
        carry += __shfl_sync(0xffffffffu, inc[c], 31);
    }

    #pragma unroll
    for (int o = 16; o > 0; o >>= 1) {
        r0  += __shfl_xor_sync(0xffffffffu, r0,  o);
        r1  += __shfl_xor_sync(0xffffffffu, r1,  o);
        r2  += __shfl_xor_sync(0xffffffffu, r2,  o);
        dep += __shfl_xor_sync(0xffffffffu, dep, o);
    }
    if (lane == 0) {
        out[3*ray+0]     = r0;
        out[3*ray+1]     = r1;
        out[3*ray+2]     = r2;
        out[3*NB_ + ray] = dep;
    }
}

// ---------------------------------------------------------------------------
extern "C" void kernel_launch(void* const* d_in, const int* in_sizes, int n_in,
                              void* d_out, int out_size)
{
    const float* rays_o   = (const float*)d_in[0];
    const float* rays_d   = (const float*)d_in[1];
    const float* viewdirs = (const float*)d_in[2];
    const float* grid     = (const float*)d_in[3];
    const float* Wf       = (const float*)d_in[4];
    const float* bf       = (const float*)d_in[5];
    const float* W1       = (const float*)d_in[6];
    const float* b1       = (const float*)d_in[7];
    const float* W2       = (const float*)d_in[8];
    const float* b2       = (const float*)d_in[9];
    const float* beta     = (const float*)d_in[10];

    // ncu captures our 0-based launch index 3 -> mlp_kernel there.
    prep_kernel<<<1, 256>>>(Wf, bf, W1, b1);                 // resets g_total
    interval_kernel<<<NB_/8, 256>>>(rays_o, rays_d);
    trilerp_kernel<<<1184, 128>>>(rays_o, rays_d, viewdirs, grid);
    mlp_kernel<<<740, 128>>>(W1, W2, b2);
    ray_kernel<<<NB_, 32>>>(rays_d, beta, (float*)d_out);
}